// round 6
// baseline (speedup 1.0000x reference)
#include <cuda_runtime.h>
#include <math.h>

// Problem-size constants (fixed by the dataset)
#define NMAX 50000
#define EMAX 800000
#define ETMAX (NMAX + EMAX)

// ---------------- scratch (static device globals; no allocation) ----------------
__device__ float  g_bufA[(size_t)NMAX * 256];   // h = in @ W
__device__ float  g_bufB[(size_t)NMAX * 256];   // aggregated output / next layer input
__device__ float  g_s[NMAX * 4];
__device__ float  g_d[NMAX * 4];
__device__ float  g_m[NMAX * 4];
__device__ float  g_den[NMAX * 4];
__device__ float  g_e[(size_t)ETMAX * 4];
__device__ int    g_src[ETMAX];
__device__ int    g_dst[ETMAX];
__device__ int    g_is64;
__device__ double g_sum[256];
__device__ double g_sq[256];
__device__ float  g_scale[256];
__device__ float  g_shift[256];
__device__ double g_psum[64];
__device__ float  g_pmax[64];

// Ordered-int trick: works for mixed-sign floats, init with -inf.
__device__ __forceinline__ void atomicMaxF(float* addr, float v) {
    if (v >= 0.f) atomicMax((int*)addr, __float_as_int(v));
    else          atomicMin((unsigned int*)addr, __float_as_uint(v));
}

// ---------------- edge-index dtype detection + conversion ----------------------
// If the buffer is int64 (little-endian, values in [0, 2^31)), every odd int32
// word of the first 128 pairs is 0. For genuine int32 random indices in
// [0, 50000) that is astronomically improbable.
__global__ void k_detect(const int* __restrict__ ei32) {
    if (threadIdx.x == 0) {
        int is64 = 1;
        for (int k = 0; k < 128; k++)
            if (ei32[2 * k + 1] != 0) { is64 = 0; break; }
        g_is64 = is64;
    }
}

__global__ void k_cvt(const int* __restrict__ ei32, int E, int ET) {
    int i = blockIdx.x * blockDim.x + threadIdx.x;
    if (i >= ET) return;
    int s, d;
    if (i < E) {
        if (g_is64) { s = ei32[2 * (size_t)i]; d = ei32[2 * ((size_t)E + i)]; }
        else        { s = ei32[i];             d = ei32[E + i]; }
    } else {
        s = d = i - E;   // self-loops
    }
    g_src[i] = s;
    g_dst[i] = d;
}

// ---------------- SGEMM: C[M,N] = A[M,K] @ B[K,N], row-major, N%64==0, K%16==0 ----
__global__ void k_sgemm(const float* __restrict__ A, const float* __restrict__ B,
                        float* __restrict__ C, int M, int N, int K) {
    __shared__ float As[16][68];   // [k][m], padded
    __shared__ float Bs[16][64];   // [k][n]
    const int tid = threadIdx.y * 16 + threadIdx.x;
    const int rb = blockIdx.y * 64, cb = blockIdx.x * 64;
    const int ar = tid >> 2, ac = (tid & 3) * 4;     // A tile: 64 rows x 16 cols
    const int br = tid >> 4, bc = (tid & 15) * 4;    // B tile: 16 rows x 64 cols
    float acc[4][4] = {};
    for (int k0 = 0; k0 < K; k0 += 16) {
        float4 av = make_float4(0.f, 0.f, 0.f, 0.f);
        if (rb + ar < M) av = *(const float4*)(A + (size_t)(rb + ar) * K + k0 + ac);
        float4 bv = *(const float4*)(B + (size_t)(k0 + br) * N + cb + bc);
        __syncthreads();
        As[ac + 0][ar] = av.x; As[ac + 1][ar] = av.y;
        As[ac + 2][ar] = av.z; As[ac + 3][ar] = av.w;
        *(float4*)&Bs[br][bc] = bv;
        __syncthreads();
#pragma unroll
        for (int kk = 0; kk < 16; kk++) {
            float a[4], b[4];
#pragma unroll
            for (int i = 0; i < 4; i++) a[i] = As[kk][threadIdx.y * 4 + i];
#pragma unroll
            for (int j = 0; j < 4; j++) b[j] = Bs[kk][threadIdx.x * 4 + j];
#pragma unroll
            for (int i = 0; i < 4; i++)
#pragma unroll
                for (int j = 0; j < 4; j++) acc[i][j] += a[i] * b[j];
        }
    }
#pragma unroll
    for (int i = 0; i < 4; i++) {
        int r = rb + threadIdx.y * 4 + i;
        if (r < M) {
            float4 v = make_float4(acc[i][0], acc[i][1], acc[i][2], acc[i][3]);
            *(float4*)(C + (size_t)r * N + cb + threadIdx.x * 4) = v;
        }
    }
}

// ---------------- per-(node,head) attention coefficients s,d -------------------
__global__ void k_sd(const float* __restrict__ h, const float* __restrict__ asrc,
                     const float* __restrict__ adst, int Nn, int H) {
    int w = (int)((blockIdx.x * (size_t)blockDim.x + threadIdx.x) >> 5);
    int lane = threadIdx.x & 31;
    if (w >= Nn * H) return;
    int n = w / H, hh = w - n * H;
    const float* hp = h + (size_t)n * H * 64 + hh * 64;
    float x0 = hp[lane], x1 = hp[lane + 32];
    float sv = x0 * asrc[hh * 64 + lane] + x1 * asrc[hh * 64 + lane + 32];
    float dv = x0 * adst[hh * 64 + lane] + x1 * adst[hh * 64 + lane + 32];
#pragma unroll
    for (int o = 16; o; o >>= 1) {
        sv += __shfl_xor_sync(0xffffffffu, sv, o);
        dv += __shfl_xor_sync(0xffffffffu, dv, o);
    }
    if (lane == 0) { g_s[w] = sv; g_d[w] = dv; }
}

__global__ void k_init(int nH) {
    int i = blockIdx.x * blockDim.x + threadIdx.x;
    if (i < nH) { g_m[i] = -INFINITY; g_den[i] = 0.f; }
}

// ---------------- edge pass 1: leaky-relu logits + segment max -----------------
__global__ void k_edge_logits(int ET, int H) {
    int i = blockIdx.x * blockDim.x + threadIdx.x;
    if (i >= ET) return;
    int src = g_src[i], dst = g_dst[i];
    for (int h = 0; h < H; h++) {
        float v = g_s[src * H + h] + g_d[dst * H + h];
        v = v > 0.f ? v : 0.2f * v;
        g_e[(size_t)i * H + h] = v;
        atomicMaxF(&g_m[dst * H + h], v);
    }
}

// ---------------- edge pass 2: exp + segment sum -------------------------------
__global__ void k_edge_exp(int ET, int H) {
    int i = blockIdx.x * blockDim.x + threadIdx.x;
    if (i >= ET) return;
    int dst = g_dst[i];
    for (int h = 0; h < H; h++) {
        float v = expf(g_e[(size_t)i * H + h] - g_m[dst * H + h]);
        g_e[(size_t)i * H + h] = v;
        atomicAdd(&g_den[dst * H + h], v);
    }
}

// ---------------- edge pass 3: weighted scatter-add (HC=256, H=4) --------------
__global__ void k_aggr256(int ET) {
    int w = (int)((blockIdx.x * (size_t)blockDim.x + threadIdx.x) >> 5);
    int lane = threadIdx.x & 31;
    if (w >= ET) return;
    int src = g_src[w], dst = g_dst[w];
    int h0 = lane >> 4;  // head of channels [lane*4 .. lane*4+3]
    float a0 = g_e[(size_t)w * 4 + h0]     / (g_den[dst * 4 + h0]     + 1e-16f);
    float a1 = g_e[(size_t)w * 4 + 2 + h0] / (g_den[dst * 4 + 2 + h0] + 1e-16f);
    const float4* hp = (const float4*)(g_bufA + (size_t)src * 256);
    float4 v0 = hp[lane], v1 = hp[lane + 32];
    v0.x *= a0; v0.y *= a0; v0.z *= a0; v0.w *= a0;
    v1.x *= a1; v1.y *= a1; v1.z *= a1; v1.w *= a1;
    float4* op = (float4*)(g_bufB + (size_t)dst * 256);
    atomicAdd(op + lane, v0);          // sm_90+ vector atomic
    atomicAdd(op + lane + 32, v1);
}

// ---------------- edge pass 3: HC=64, H=1 --------------------------------------
__global__ void k_aggr64(int ET) {
    int w = (int)((blockIdx.x * (size_t)blockDim.x + threadIdx.x) >> 5);
    int lane = threadIdx.x & 31;
    if (w >= ET) return;
    int src = g_src[w], dst = g_dst[w];
    float a = g_e[w] / (g_den[dst] + 1e-16f);
    float2 v = ((const float2*)(g_bufA + (size_t)src * 64))[lane];
    v.x *= a; v.y *= a;
    atomicAdd(((float2*)(g_bufB + (size_t)dst * 64)) + lane, v);
}

// ---------------- batchnorm stats (on x + bias) --------------------------------
__global__ void k_bnstats(const float* __restrict__ X, const float* __restrict__ bias,
                          int Nn, int HC) {
    int tid = threadIdx.x;
    int ch = tid & (HC - 1);
    int rpb = blockDim.x / HC;
    int r = blockIdx.x * rpb + tid / HC;
    int stride = gridDim.x * rpb;
    float b = bias[ch];
    float s = 0.f, q = 0.f;
    for (; r < Nn; r += stride) {
        float x = X[(size_t)r * HC + ch] + b;
        s += x; q += x * x;
    }
    atomicAdd(&g_sum[ch], (double)s);
    atomicAdd(&g_sq[ch], (double)q);
}

__global__ void k_bnfin(const float* __restrict__ gamma, const float* __restrict__ beta,
                        const float* __restrict__ bias, int Nn, int HC) {
    int ch = threadIdx.x;
    if (ch >= HC) return;
    double mu = g_sum[ch] / Nn;
    double var = g_sq[ch] / Nn - mu * mu;
    float sc = (float)((double)gamma[ch] / sqrt(var + 1e-5));
    g_scale[ch] = sc;
    g_shift[ch] = beta[ch] + sc * (bias[ch] - (float)mu);
}

// y = relu(scale*x + shift), in place, vectorized
__global__ void k_bnnorm(float* __restrict__ X, int total, int HC) {
    int i = blockIdx.x * blockDim.x + threadIdx.x;
    if (i * 4 >= total) return;
    float4 v = ((float4*)X)[i];
    int c = (i * 4) & (HC - 1);
    v.x = fmaxf(fmaf(v.x, g_scale[c + 0], g_shift[c + 0]), 0.f);
    v.y = fmaxf(fmaf(v.y, g_scale[c + 1], g_shift[c + 1]), 0.f);
    v.z = fmaxf(fmaf(v.z, g_scale[c + 2], g_shift[c + 2]), 0.f);
    v.w = fmaxf(fmaf(v.w, g_scale[c + 3], g_shift[c + 3]), 0.f);
    ((float4*)X)[i] = v;
}

// ---------------- pooling ------------------------------------------------------
__global__ void k_initpool() {
    int i = threadIdx.x;
    if (i < 64) { g_pmax[i] = -INFINITY; g_psum[i] = 0.0; }
}

__global__ void k_pool(const float* __restrict__ X, int Nn) {
    int tid = threadIdx.x;
    int ch = tid & 63;
    int rpb = blockDim.x >> 6;
    int r = blockIdx.x * rpb + (tid >> 6);
    int stride = gridDim.x * rpb;
    float s = 0.f, mx = -INFINITY;
    for (; r < Nn; r += stride) {
        float x = X[(size_t)r * 64 + ch];
        s += x; mx = fmaxf(mx, x);
    }
    atomicAdd(&g_psum[ch], (double)s);
    atomicMaxF(&g_pmax[ch], mx);
}

// ---------------- classifier (single block) ------------------------------------
__global__ void k_cls(const float* __restrict__ Wc1, const float* __restrict__ bc1,
                      const float* __restrict__ Wc2, const float* __restrict__ bc2,
                      int Nn, float* __restrict__ out) {
    __shared__ float pooled[128];
    __shared__ float z[64];
    int t = threadIdx.x;
    if (t < 64) pooled[t] = (float)(g_psum[t] / Nn);
    else        pooled[t] = g_pmax[t - 64];
    __syncthreads();
    if (t < 64) {
        float acc = bc1[t];
        for (int k = 0; k < 128; k++) acc += pooled[k] * Wc1[k * 64 + t];
        z[t] = fmaxf(acc, 0.f);
    }
    __syncthreads();
    if (t < 2) {
        float acc = bc2[t];
        for (int j = 0; j < 64; j++) acc += z[j] * Wc2[j * 2 + t];
        out[t] = acc;
    }
}

// ---------------- driver -------------------------------------------------------
extern "C" void kernel_launch(void* const* d_in, const int* in_sizes, int n_in,
                              void* d_out, int out_size) {
    const float* x   = (const float*)d_in[0];
    const int*   ei  = (const int*)d_in[1];   // int32 OR little-endian int64; detected on device
    const float* W0  = (const float*)d_in[2];  const float* b0  = (const float*)d_in[3];
    const float* as0 = (const float*)d_in[4];  const float* ad0 = (const float*)d_in[5];
    const float* gm0 = (const float*)d_in[6];  const float* bt0 = (const float*)d_in[7];
    const float* W1  = (const float*)d_in[8];  const float* b1  = (const float*)d_in[9];
    const float* as1 = (const float*)d_in[10]; const float* ad1 = (const float*)d_in[11];
    const float* gm1 = (const float*)d_in[12]; const float* bt1 = (const float*)d_in[13];
    const float* W2  = (const float*)d_in[14]; const float* b2  = (const float*)d_in[15];
    const float* as2 = (const float*)d_in[16]; const float* ad2 = (const float*)d_in[17];
    const float* gm2 = (const float*)d_in[18]; const float* bt2 = (const float*)d_in[19];
    const float* Wc1 = (const float*)d_in[20]; const float* bc1 = (const float*)d_in[21];
    const float* Wc2 = (const float*)d_in[22]; const float* bc2 = (const float*)d_in[23];

    const int Nn = in_sizes[0] / 128;
    const int E  = in_sizes[1] / 2;   // element count is 2E for both int32 and int64
    const int ET = E + Nn;

    float* bufA; float* bufB;
    void *sumP, *sqP, *psumP;
    cudaGetSymbolAddress((void**)&bufA, g_bufA);
    cudaGetSymbolAddress((void**)&bufB, g_bufB);
    cudaGetSymbolAddress(&sumP, g_sum);
    cudaGetSymbolAddress(&sqP, g_sq);
    cudaGetSymbolAddress(&psumP, g_psum);

    // Resolve edge_index dtype on device, then materialize int32 src/dst (+self-loops)
    k_detect<<<1, 32>>>(ei);
    k_cvt<<<(ET + 255) / 256, 256>>>(ei, E, ET);

    auto run_layer = [&](const float* in, int K, const float* W, const float* bias,
                         const float* asrc, const float* adst,
                         const float* gamma, const float* beta, int H) {
        const int HC = H * 64;
        dim3 bb(16, 16), gg(HC / 64, (Nn + 63) / 64);
        k_sgemm<<<gg, bb>>>(in, W, bufA, Nn, HC, K);
        {
            long long th = (long long)Nn * H * 32;
            k_sd<<<(unsigned)((th + 255) / 256), 256>>>(bufA, asrc, adst, Nn, H);
        }
        k_init<<<(Nn * H + 255) / 256, 256>>>(Nn * H);
        cudaMemsetAsync(bufB, 0, (size_t)Nn * HC * sizeof(float), 0);
        k_edge_logits<<<(ET + 255) / 256, 256>>>(ET, H);
        k_edge_exp<<<(ET + 255) / 256, 256>>>(ET, H);
        {
            long long th = (long long)ET * 32;
            unsigned nb = (unsigned)((th + 255) / 256);
            if (HC == 256) k_aggr256<<<nb, 256>>>(ET);
            else           k_aggr64 <<<nb, 256>>>(ET);
        }
        cudaMemsetAsync(sumP, 0, HC * sizeof(double), 0);
        cudaMemsetAsync(sqP, 0, HC * sizeof(double), 0);
        k_bnstats<<<512, 256>>>(bufB, bias, Nn, HC);
        k_bnfin<<<1, 256>>>(gamma, beta, bias, Nn, HC);
        k_bnnorm<<<((Nn * HC / 4) + 255) / 256, 256>>>(bufB, Nn * HC, HC);
    };

    run_layer(x,    128, W0, b0, as0, ad0, gm0, bt0, 4);
    run_layer(bufB, 256, W1, b1, as1, ad1, gm1, bt1, 4);
    run_layer(bufB, 256, W2, b2, as2, ad2, gm2, bt2, 1);

    cudaMemsetAsync(psumP, 0, 64 * sizeof(double), 0);
    k_initpool<<<1, 64>>>();
    k_pool<<<256, 256>>>(bufB, Nn);
    k_cls<<<1, 128>>>(Wc1, bc1, Wc2, bc2, Nn, (float*)d_out);
}

// round 9
// speedup vs baseline: 1.1035x; 1.1035x over previous
#include <cuda_runtime.h>
#include <math.h>

// Problem-size constants (fixed by the dataset)
#define NMAX 50000
#define EMAX 800000
#define ETMAX (NMAX + EMAX)

// ---------------- scratch (static device globals; no allocation) ----------------
__device__ float  g_bufA[(size_t)NMAX * 256];   // h = in @ W
__device__ float  g_bufB[(size_t)NMAX * 256];   // aggregated output / next layer input
__device__ float  g_s[NMAX * 4];
__device__ float  g_d[NMAX * 4];
__device__ float  g_m[NMAX * 4];
__device__ float  g_den[NMAX * 4];
__device__ float  g_e[(size_t)ETMAX * 4];
__device__ int    g_src[ETMAX];
__device__ int    g_dst[ETMAX];
__device__ int    g_is64;
__device__ double g_sum[256];
__device__ double g_sq[256];
__device__ float  g_scale[256];
__device__ float  g_shift[256];
__device__ double g_psum[64];
__device__ float  g_pmax[64];

// Ordered-int trick: works for mixed-sign floats, init with -inf.
__device__ __forceinline__ void atomicMaxF(float* addr, float v) {
    if (v >= 0.f) atomicMax((int*)addr, __float_as_int(v));
    else          atomicMin((unsigned int*)addr, __float_as_uint(v));
}

// ---------------- edge-index dtype detection + conversion ----------------------
__global__ void k_detect(const int* __restrict__ ei32) {
    if (threadIdx.x == 0) {
        int is64 = 1;
        for (int k = 0; k < 128; k++)
            if (ei32[2 * k + 1] != 0) { is64 = 0; break; }
        g_is64 = is64;
    }
}

__global__ void k_cvt(const int* __restrict__ ei32, int E, int ET) {
    int i = blockIdx.x * blockDim.x + threadIdx.x;
    if (i >= ET) return;
    int s, d;
    if (i < E) {
        if (g_is64) { s = ei32[2 * (size_t)i]; d = ei32[2 * ((size_t)E + i)]; }
        else        { s = ei32[i];             d = ei32[E + i]; }
    } else {
        s = d = i - E;   // self-loops
    }
    g_src[i] = s;
    g_dst[i] = d;
}

// ---------------- high-throughput SGEMM ----------------------------------------
// C[M,N] = BNReLU(A)[M,K] @ B[K,N]. Row-major. K%16==0, N%TN==0.
// 8x8 micro-tile split as 2x2 blocks of 4x4 (conflict-free LDS.128),
// double-buffered shared tiles, register-staged global prefetch.
// Flat loops (no lambdas) for compile robustness.
template<int TM, int TN>
__global__ void __launch_bounds__((TM/8)*(TN/8))
k_sgemm_opt(const float* __restrict__ A, const float* __restrict__ B,
            float* __restrict__ C, int M, int N, int K,
            const float* __restrict__ bnscale, const float* __restrict__ bnshift) {
    constexpr int BK = 16;
    constexpr int NT = (TM / 8) * (TN / 8);     // threads per block
    constexpr int AV = TM * BK / 4 / NT;        // float4 A loads / thread / step
    constexpr int BV = BK * TN / 4 / NT;        // float4 B loads / thread / step
    __shared__ float As[2][BK][TM + 4];
    __shared__ float Bs[2][BK][TN];

    const int tid = threadIdx.x;
    const int tx = tid % (TN / 8);
    const int ty = tid / (TN / 8);
    const int rb = blockIdx.y * TM;
    const int cb = blockIdx.x * TN;

    float4 aF[AV], bF[BV];
    float acc[8][8];
#pragma unroll
    for (int i = 0; i < 8; i++)
#pragma unroll
        for (int j = 0; j < 8; j++) acc[i][j] = 0.f;

    // ---- prologue: global load of k-slab 0 into registers
#pragma unroll
    for (int i = 0; i < AV; i++) {
        const int idx = tid + i * NT;
        const int r = idx / (BK / 4);
        const int c = (idx % (BK / 4)) * 4;
        float4 v = make_float4(0.f, 0.f, 0.f, 0.f);
        if (rb + r < M) v = *(const float4*)(A + (size_t)(rb + r) * K + c);
        if (bnscale) {
            float4 sc = *(const float4*)(bnscale + c);
            float4 sh = *(const float4*)(bnshift + c);
            v.x = fmaxf(fmaf(v.x, sc.x, sh.x), 0.f);
            v.y = fmaxf(fmaf(v.y, sc.y, sh.y), 0.f);
            v.z = fmaxf(fmaf(v.z, sc.z, sh.z), 0.f);
            v.w = fmaxf(fmaf(v.w, sc.w, sh.w), 0.f);
        }
        aF[i] = v;
    }
#pragma unroll
    for (int i = 0; i < BV; i++) {
        const int idx = tid + i * NT;
        const int r = idx / (TN / 4);
        const int c = (idx % (TN / 4)) * 4;
        bF[i] = *(const float4*)(B + (size_t)r * N + cb + c);
    }
    // store slab 0 into buffer 0
#pragma unroll
    for (int i = 0; i < AV; i++) {
        const int idx = tid + i * NT;
        const int r = idx / (BK / 4);
        const int c = (idx % (BK / 4)) * 4;
        As[0][c + 0][r] = aF[i].x;
        As[0][c + 1][r] = aF[i].y;
        As[0][c + 2][r] = aF[i].z;
        As[0][c + 3][r] = aF[i].w;
    }
#pragma unroll
    for (int i = 0; i < BV; i++) {
        const int idx = tid + i * NT;
        const int r = idx / (TN / 4);
        const int c = (idx % (TN / 4)) * 4;
        *(float4*)&Bs[0][r][c] = bF[i];
    }
    __syncthreads();

    int buf = 0;
    for (int k0 = BK; k0 < K; k0 += BK) {
        // global load of next k-slab into registers
#pragma unroll
        for (int i = 0; i < AV; i++) {
            const int idx = tid + i * NT;
            const int r = idx / (BK / 4);
            const int c = (idx % (BK / 4)) * 4;
            float4 v = make_float4(0.f, 0.f, 0.f, 0.f);
            if (rb + r < M) v = *(const float4*)(A + (size_t)(rb + r) * K + k0 + c);
            if (bnscale) {
                float4 sc = *(const float4*)(bnscale + k0 + c);
                float4 sh = *(const float4*)(bnshift + k0 + c);
                v.x = fmaxf(fmaf(v.x, sc.x, sh.x), 0.f);
                v.y = fmaxf(fmaf(v.y, sc.y, sh.y), 0.f);
                v.z = fmaxf(fmaf(v.z, sc.z, sh.z), 0.f);
                v.w = fmaxf(fmaf(v.w, sc.w, sh.w), 0.f);
            }
            aF[i] = v;
        }
#pragma unroll
        for (int i = 0; i < BV; i++) {
            const int idx = tid + i * NT;
            const int r = idx / (TN / 4);
            const int c = (idx % (TN / 4)) * 4;
            bF[i] = *(const float4*)(B + (size_t)(k0 + r) * N + cb + c);
        }
        // compute on current buffer
#pragma unroll
        for (int kk = 0; kk < BK; kk++) {
            float a[8], b[8];
            *(float4*)&a[0] = *(const float4*)&As[buf][kk][ty * 4];
            *(float4*)&a[4] = *(const float4*)&As[buf][kk][TM / 2 + ty * 4];
            *(float4*)&b[0] = *(const float4*)&Bs[buf][kk][tx * 4];
            *(float4*)&b[4] = *(const float4*)&Bs[buf][kk][TN / 2 + tx * 4];
#pragma unroll
            for (int i = 0; i < 8; i++)
#pragma unroll
                for (int j = 0; j < 8; j++)
                    acc[i][j] = fmaf(a[i], b[j], acc[i][j]);
        }
        // store prefetched slab into the other buffer
#pragma unroll
        for (int i = 0; i < AV; i++) {
            const int idx = tid + i * NT;
            const int r = idx / (BK / 4);
            const int c = (idx % (BK / 4)) * 4;
            As[buf ^ 1][c + 0][r] = aF[i].x;
            As[buf ^ 1][c + 1][r] = aF[i].y;
            As[buf ^ 1][c + 2][r] = aF[i].z;
            As[buf ^ 1][c + 3][r] = aF[i].w;
        }
#pragma unroll
        for (int i = 0; i < BV; i++) {
            const int idx = tid + i * NT;
            const int r = idx / (TN / 4);
            const int c = (idx % (TN / 4)) * 4;
            *(float4*)&Bs[buf ^ 1][r][c] = bF[i];
        }
        __syncthreads();
        buf ^= 1;
    }
    // tail compute on the last buffer
#pragma unroll
    for (int kk = 0; kk < BK; kk++) {
        float a[8], b[8];
        *(float4*)&a[0] = *(const float4*)&As[buf][kk][ty * 4];
        *(float4*)&a[4] = *(const float4*)&As[buf][kk][TM / 2 + ty * 4];
        *(float4*)&b[0] = *(const float4*)&Bs[buf][kk][tx * 4];
        *(float4*)&b[4] = *(const float4*)&Bs[buf][kk][TN / 2 + tx * 4];
#pragma unroll
        for (int i = 0; i < 8; i++)
#pragma unroll
            for (int j = 0; j < 8; j++)
                acc[i][j] = fmaf(a[i], b[j], acc[i][j]);
    }

#pragma unroll
    for (int i = 0; i < 8; i++) {
        int r = rb + (i < 4 ? ty * 4 + i : TM / 2 + ty * 4 + (i - 4));
        if (r < M) {
            float4 v0 = make_float4(acc[i][0], acc[i][1], acc[i][2], acc[i][3]);
            float4 v1 = make_float4(acc[i][4], acc[i][5], acc[i][6], acc[i][7]);
            *(float4*)(C + (size_t)r * N + cb + tx * 4) = v0;
            *(float4*)(C + (size_t)r * N + cb + TN / 2 + tx * 4) = v1;
        }
    }
}

// ---------------- per-(node,head) attention coefficients s,d -------------------
__global__ void k_sd(const float* __restrict__ h, const float* __restrict__ asrc,
                     const float* __restrict__ adst, int Nn, int H) {
    int w = (int)((blockIdx.x * (size_t)blockDim.x + threadIdx.x) >> 5);
    int lane = threadIdx.x & 31;
    if (w >= Nn * H) return;
    int n = w / H, hh = w - n * H;
    const float* hp = h + (size_t)n * H * 64 + hh * 64;
    float x0 = hp[lane], x1 = hp[lane + 32];
    float sv = x0 * asrc[hh * 64 + lane] + x1 * asrc[hh * 64 + lane + 32];
    float dv = x0 * adst[hh * 64 + lane] + x1 * adst[hh * 64 + lane + 32];
#pragma unroll
    for (int o = 16; o; o >>= 1) {
        sv += __shfl_xor_sync(0xffffffffu, sv, o);
        dv += __shfl_xor_sync(0xffffffffu, dv, o);
    }
    if (lane == 0) { g_s[w] = sv; g_d[w] = dv; }
}

__global__ void k_init(int nH) {
    int i = blockIdx.x * blockDim.x + threadIdx.x;
    if (i < nH) { g_m[i] = -INFINITY; g_den[i] = 0.f; }
}

// ---------------- edge pass 1: logits + segment max (H=4, vectorized) ----------
__global__ void k_edge_logits4(int ET) {
    int i = blockIdx.x * blockDim.x + threadIdx.x;
    if (i >= ET) return;
    int src = g_src[i], dst = g_dst[i];
    float4 s = *(const float4*)&g_s[src * 4];
    float4 d = *(const float4*)&g_d[dst * 4];
    float4 v;
    v.x = s.x + d.x; v.x = v.x > 0.f ? v.x : 0.2f * v.x;
    v.y = s.y + d.y; v.y = v.y > 0.f ? v.y : 0.2f * v.y;
    v.z = s.z + d.z; v.z = v.z > 0.f ? v.z : 0.2f * v.z;
    v.w = s.w + d.w; v.w = v.w > 0.f ? v.w : 0.2f * v.w;
    *(float4*)&g_e[(size_t)i * 4] = v;
    atomicMaxF(&g_m[dst * 4 + 0], v.x);
    atomicMaxF(&g_m[dst * 4 + 1], v.y);
    atomicMaxF(&g_m[dst * 4 + 2], v.z);
    atomicMaxF(&g_m[dst * 4 + 3], v.w);
}

__global__ void k_edge_logits1(int ET) {
    int i = blockIdx.x * blockDim.x + threadIdx.x;
    if (i >= ET) return;
    int src = g_src[i], dst = g_dst[i];
    float v = g_s[src] + g_d[dst];
    v = v > 0.f ? v : 0.2f * v;
    g_e[i] = v;
    atomicMaxF(&g_m[dst], v);
}

// ---------------- edge pass 2: exp + segment sum --------------------------------
__global__ void k_edge_exp4(int ET) {
    int i = blockIdx.x * blockDim.x + threadIdx.x;
    if (i >= ET) return;
    int dst = g_dst[i];
    float4 e = *(const float4*)&g_e[(size_t)i * 4];
    float4 m = *(const float4*)&g_m[dst * 4];
    float4 v;
    v.x = expf(e.x - m.x);
    v.y = expf(e.y - m.y);
    v.z = expf(e.z - m.z);
    v.w = expf(e.w - m.w);
    *(float4*)&g_e[(size_t)i * 4] = v;
    atomicAdd((float4*)&g_den[dst * 4], v);   // one 16B atomic, same dst per component
}

__global__ void k_edge_exp1(int ET) {
    int i = blockIdx.x * blockDim.x + threadIdx.x;
    if (i >= ET) return;
    int dst = g_dst[i];
    float v = expf(g_e[i] - g_m[dst]);
    g_e[i] = v;
    atomicAdd(&g_den[dst], v);
}

// ---------------- edge pass 3: weighted scatter-add (HC=256, H=4) --------------
__global__ void k_aggr256(int ET) {
    int w = (int)((blockIdx.x * (size_t)blockDim.x + threadIdx.x) >> 5);
    int lane = threadIdx.x & 31;
    if (w >= ET) return;
    int src = g_src[w], dst = g_dst[w];
    int h0 = lane >> 4;  // head of channels [lane*4 .. lane*4+3]
    float a0 = g_e[(size_t)w * 4 + h0]     / (g_den[dst * 4 + h0]     + 1e-16f);
    float a1 = g_e[(size_t)w * 4 + 2 + h0] / (g_den[dst * 4 + 2 + h0] + 1e-16f);
    const float4* hp = (const float4*)(g_bufA + (size_t)src * 256);
    float4 v0 = hp[lane], v1 = hp[lane + 32];
    v0.x *= a0; v0.y *= a0; v0.z *= a0; v0.w *= a0;
    v1.x *= a1; v1.y *= a1; v1.z *= a1; v1.w *= a1;
    float4* op = (float4*)(g_bufB + (size_t)dst * 256);
    atomicAdd(op + lane, v0);
    atomicAdd(op + lane + 32, v1);
}

// ---------------- edge pass 3: HC=64, H=1 --------------------------------------
__global__ void k_aggr64(int ET) {
    int w = (int)((blockIdx.x * (size_t)blockDim.x + threadIdx.x) >> 5);
    int lane = threadIdx.x & 31;
    if (w >= ET) return;
    int src = g_src[w], dst = g_dst[w];
    float a = g_e[w] / (g_den[dst] + 1e-16f);
    float2 v = ((const float2*)(g_bufA + (size_t)src * 64))[lane];
    v.x *= a; v.y *= a;
    atomicAdd(((float2*)(g_bufB + (size_t)dst * 64)) + lane, v);
}

// ---------------- batchnorm stats (on x + bias) --------------------------------
__global__ void k_bnstats(const float* __restrict__ X, const float* __restrict__ bias,
                          int Nn, int HC) {
    int tid = threadIdx.x;
    int ch = tid & (HC - 1);
    int rpb = blockDim.x / HC;
    int r = blockIdx.x * rpb + tid / HC;
    int stride = gridDim.x * rpb;
    float b = bias[ch];
    float s = 0.f, q = 0.f;
    for (; r < Nn; r += stride) {
        float x = X[(size_t)r * HC + ch] + b;
        s += x; q += x * x;
    }
    atomicAdd(&g_sum[ch], (double)s);
    atomicAdd(&g_sq[ch], (double)q);
}

__global__ void k_bnfin(const float* __restrict__ gamma, const float* __restrict__ beta,
                        const float* __restrict__ bias, int Nn, int HC) {
    int ch = threadIdx.x;
    if (ch >= HC) return;
    double mu = g_sum[ch] / Nn;
    double var = g_sq[ch] / Nn - mu * mu;
    float sc = (float)((double)gamma[ch] / sqrt(var + 1e-5));
    g_scale[ch] = sc;
    g_shift[ch] = beta[ch] + sc * (bias[ch] - (float)mu);
}

// ---------------- pooling (applies layer-2 BN + ReLU inline) -------------------
__global__ void k_initpool() {
    int i = threadIdx.x;
    if (i < 64) { g_pmax[i] = -INFINITY; g_psum[i] = 0.0; }
}

__global__ void k_pool(const float* __restrict__ X, int Nn) {
    int tid = threadIdx.x;
    int ch = tid & 63;
    int rpb = blockDim.x >> 6;
    int r = blockIdx.x * rpb + (tid >> 6);
    int stride = gridDim.x * rpb;
    float sc = g_scale[ch], sh = g_shift[ch];
    float s = 0.f, mx = -INFINITY;
    for (; r < Nn; r += stride) {
        float x = fmaxf(fmaf(X[(size_t)r * 64 + ch], sc, sh), 0.f);
        s += x; mx = fmaxf(mx, x);
    }
    atomicAdd(&g_psum[ch], (double)s);
    atomicMaxF(&g_pmax[ch], mx);
}

// ---------------- classifier (single block) ------------------------------------
__global__ void k_cls(const float* __restrict__ Wc1, const float* __restrict__ bc1,
                      const float* __restrict__ Wc2, const float* __restrict__ bc2,
                      int Nn, float* __restrict__ out) {
    __shared__ float pooled[128];
    __shared__ float z[64];
    int t = threadIdx.x;
    if (t < 64) pooled[t] = (float)(g_psum[t] / Nn);
    else        pooled[t] = g_pmax[t - 64];
    __syncthreads();
    if (t < 64) {
        float acc = bc1[t];
        for (int k = 0; k < 128; k++) acc += pooled[k] * Wc1[k * 64 + t];
        z[t] = fmaxf(acc, 0.f);
    }
    __syncthreads();
    if (t < 2) {
        float acc = bc2[t];
        for (int j = 0; j < 64; j++) acc += z[j] * Wc2[j * 2 + t];
        out[t] = acc;
    }
}

// ---------------- driver -------------------------------------------------------
extern "C" void kernel_launch(void* const* d_in, const int* in_sizes, int n_in,
                              void* d_out, int out_size) {
    const float* x   = (const float*)d_in[0];
    const int*   ei  = (const int*)d_in[1];   // int32 OR little-endian int64; detected on device
    const float* W0  = (const float*)d_in[2];  const float* b0  = (const float*)d_in[3];
    const float* as0 = (const float*)d_in[4];  const float* ad0 = (const float*)d_in[5];
    const float* gm0 = (const float*)d_in[6];  const float* bt0 = (const float*)d_in[7];
    const float* W1  = (const float*)d_in[8];  const float* b1  = (const float*)d_in[9];
    const float* as1 = (const float*)d_in[10]; const float* ad1 = (const float*)d_in[11];
    const float* gm1 = (const float*)d_in[12]; const float* bt1 = (const float*)d_in[13];
    const float* W2  = (const float*)d_in[14]; const float* b2  = (const float*)d_in[15];
    const float* as2 = (const float*)d_in[16]; const float* ad2 = (const float*)d_in[17];
    const float* gm2 = (const float*)d_in[18]; const float* bt2 = (const float*)d_in[19];
    const float* Wc1 = (const float*)d_in[20]; const float* bc1 = (const float*)d_in[21];
    const float* Wc2 = (const float*)d_in[22]; const float* bc2 = (const float*)d_in[23];

    const int Nn = in_sizes[0] / 128;
    const int E  = in_sizes[1] / 2;
    const int ET = E + Nn;

    float* bufA; float* bufB; float* scaleP; float* shiftP;
    void *sumP, *sqP, *psumP;
    cudaGetSymbolAddress((void**)&bufA, g_bufA);
    cudaGetSymbolAddress((void**)&bufB, g_bufB);
    cudaGetSymbolAddress((void**)&scaleP, g_scale);
    cudaGetSymbolAddress((void**)&shiftP, g_shift);
    cudaGetSymbolAddress(&sumP, g_sum);
    cudaGetSymbolAddress(&sqP, g_sq);
    cudaGetSymbolAddress(&psumP, g_psum);

    // Resolve edge_index dtype on device, then materialize int32 src/dst (+self-loops)
    k_detect<<<1, 32>>>(ei);
    k_cvt<<<(ET + 255) / 256, 256>>>(ei, E, ET);

    auto run_layer = [&](const float* in, int K, const float* W, const float* bias,
                         const float* asrc, const float* adst,
                         const float* gamma, const float* beta, int H, bool bnA) {
        const int HC = H * 64;
        // GEMM (BN+ReLU of previous layer folded into A-load when bnA)
        const float* sc = bnA ? scaleP : nullptr;
        const float* sh = bnA ? shiftP : nullptr;
        if (HC == 256)
            k_sgemm_opt<128, 128><<<dim3(2, (Nn + 127) / 128), 256>>>(in, W, bufA, Nn, 256, K, sc, sh);
        else
            k_sgemm_opt<128, 64><<<dim3(1, (Nn + 127) / 128), 128>>>(in, W, bufA, Nn, 64, K, sc, sh);
        {
            long long th = (long long)Nn * H * 32;
            k_sd<<<(unsigned)((th + 255) / 256), 256>>>(bufA, asrc, adst, Nn, H);
        }
        k_init<<<(Nn * H + 255) / 256, 256>>>(Nn * H);
        cudaMemsetAsync(bufB, 0, (size_t)Nn * HC * sizeof(float), 0);
        if (H == 4) {
            k_edge_logits4<<<(ET + 255) / 256, 256>>>(ET);
            k_edge_exp4<<<(ET + 255) / 256, 256>>>(ET);
        } else {
            k_edge_logits1<<<(ET + 255) / 256, 256>>>(ET);
            k_edge_exp1<<<(ET + 255) / 256, 256>>>(ET);
        }
        {
            long long th = (long long)ET * 32;
            unsigned nb = (unsigned)((th + 255) / 256);
            if (HC == 256) k_aggr256<<<nb, 256>>>(ET);
            else           k_aggr64 <<<nb, 256>>>(ET);
        }
        cudaMemsetAsync(sumP, 0, HC * sizeof(double), 0);
        cudaMemsetAsync(sqP, 0, HC * sizeof(double), 0);
        k_bnstats<<<512, 256>>>(bufB, bias, Nn, HC);
        k_bnfin<<<1, 256>>>(gamma, beta, bias, Nn, HC);
        // NOTE: no normalize pass — BN+ReLU is consumed by the next GEMM / k_pool.
    };

    run_layer(x,    128, W0, b0, as0, ad0, gm0, bt0, 4, false);
    run_layer(bufB, 256, W1, b1, as1, ad1, gm1, bt1, 4, true);
    run_layer(bufB, 256, W2, b2, as2, ad2, gm2, bt2, 1, true);

    cudaMemsetAsync(psumP, 0, 64 * sizeof(double), 0);
    k_initpool<<<1, 64>>>();
    k_pool<<<256, 256>>>(bufB, Nn);   // applies layer-2 BN+ReLU inline
    k_cls<<<1, 128>>>(Wc1, bc1, Wc2, bc2, Nn, (float*)d_out);
}

// round 12
// speedup vs baseline: 1.2806x; 1.1605x over previous
#include <cuda_runtime.h>
#include <math.h>

// Problem-size constants (fixed by the dataset)
#define NMAX 50000
#define EMAX 800000
#define ETMAX (NMAX + EMAX)

// ---------------- scratch (static device globals; no allocation) ----------------
__device__ float  g_bufA[(size_t)NMAX * 256];   // h = in @ W
__device__ float  g_bufB[(size_t)NMAX * 256];   // aggregated output / next layer input
__device__ float  g_s[NMAX * 4];
__device__ float  g_d[NMAX * 4];
__device__ float  g_m[NMAX * 4];
__device__ float  g_den[NMAX * 4];
__device__ int    g_src[ETMAX];
__device__ int    g_dst[ETMAX];
__device__ int    g_deg[NMAX];
__device__ int    g_rowstart[NMAX + 1];
__device__ int    g_cursor[NMAX];
__device__ int    g_csr_src[ETMAX];
__device__ int    g_is64;
__device__ double g_sum[256];
__device__ double g_sq[256];
__device__ float  g_scale[256];
__device__ float  g_shift[256];
__device__ double g_psum[64];
__device__ float  g_pmax[64];

// Ordered-int trick: works for mixed-sign floats, init with -inf.
__device__ __forceinline__ void atomicMaxF(float* addr, float v) {
    if (v >= 0.f) atomicMax((int*)addr, __float_as_int(v));
    else          atomicMin((unsigned int*)addr, __float_as_uint(v));
}

// ---------------- edge-index dtype detection + conversion ----------------------
__global__ void k_detect(const int* __restrict__ ei32) {
    if (threadIdx.x == 0) {
        int is64 = 1;
        for (int k = 0; k < 128; k++)
            if (ei32[2 * k + 1] != 0) { is64 = 0; break; }
        g_is64 = is64;
    }
}

__global__ void k_cvt(const int* __restrict__ ei32, int E, int ET) {
    int i = blockIdx.x * blockDim.x + threadIdx.x;
    if (i >= ET) return;
    int s, d;
    if (i < E) {
        if (g_is64) { s = ei32[2 * (size_t)i]; d = ei32[2 * ((size_t)E + i)]; }
        else        { s = ei32[i];             d = ei32[E + i]; }
    } else {
        s = d = i - E;   // self-loops
    }
    g_src[i] = s;
    g_dst[i] = d;
}

// ---------------- CSR build: histogram -> scan -> scatter ----------------------
__global__ void k_hist(int ET) {
    int i = blockIdx.x * blockDim.x + threadIdx.x;
    if (i < ET) atomicAdd(&g_deg[g_dst[i]], 1);
}

// Single-block exclusive scan over g_deg (Nn <= 50000), 1024 threads.
__global__ void k_scan(int Nn) {
    __shared__ int tmp[1024];
    __shared__ int carry_s;
    int t = threadIdx.x;
    if (t == 0) carry_s = 0;
    __syncthreads();
    for (int base = 0; base < Nn; base += 1024) {
        int v = (base + t < Nn) ? g_deg[base + t] : 0;
        tmp[t] = v;
        __syncthreads();
        for (int off = 1; off < 1024; off <<= 1) {
            int x = (t >= off) ? tmp[t - off] : 0;
            __syncthreads();
            tmp[t] += x;
            __syncthreads();
        }
        int carry = carry_s;
        if (base + t < Nn) {
            int excl = carry + tmp[t] - v;
            g_rowstart[base + t] = excl;
            g_cursor[base + t] = excl;
        }
        __syncthreads();
        if (t == 0) carry_s = carry + tmp[1023];
        __syncthreads();
    }
    if (t == 0) g_rowstart[Nn] = carry_s;
}

__global__ void k_scatter(int ET) {
    int i = blockIdx.x * blockDim.x + threadIdx.x;
    if (i >= ET) return;
    int pos = atomicAdd(&g_cursor[g_dst[i]], 1);
    g_csr_src[pos] = g_src[i];
}

// ---------------- high-throughput SGEMM ----------------------------------------
// C[M,N] = BNReLU(A)[M,K] @ B[K,N]. Row-major. K%16==0, N%TN==0.
template<int TM, int TN>
__global__ void __launch_bounds__((TM/8)*(TN/8))
k_sgemm_opt(const float* __restrict__ A, const float* __restrict__ B,
            float* __restrict__ C, int M, int N, int K,
            const float* __restrict__ bnscale, const float* __restrict__ bnshift) {
    constexpr int BK = 16;
    constexpr int NT = (TM / 8) * (TN / 8);
    constexpr int AV = TM * BK / 4 / NT;
    constexpr int BV = BK * TN / 4 / NT;
    __shared__ float As[2][BK][TM + 4];
    __shared__ float Bs[2][BK][TN];

    const int tid = threadIdx.x;
    const int tx = tid % (TN / 8);
    const int ty = tid / (TN / 8);
    const int rb = blockIdx.y * TM;
    const int cb = blockIdx.x * TN;

    float4 aF[AV], bF[BV];
    float acc[8][8];
#pragma unroll
    for (int i = 0; i < 8; i++)
#pragma unroll
        for (int j = 0; j < 8; j++) acc[i][j] = 0.f;

#pragma unroll
    for (int i = 0; i < AV; i++) {
        const int idx = tid + i * NT;
        const int r = idx / (BK / 4);
        const int c = (idx % (BK / 4)) * 4;
        float4 v = make_float4(0.f, 0.f, 0.f, 0.f);
        if (rb + r < M) v = *(const float4*)(A + (size_t)(rb + r) * K + c);
        if (bnscale) {
            float4 sc = *(const float4*)(bnscale + c);
            float4 sh = *(const float4*)(bnshift + c);
            v.x = fmaxf(fmaf(v.x, sc.x, sh.x), 0.f);
            v.y = fmaxf(fmaf(v.y, sc.y, sh.y), 0.f);
            v.z = fmaxf(fmaf(v.z, sc.z, sh.z), 0.f);
            v.w = fmaxf(fmaf(v.w, sc.w, sh.w), 0.f);
        }
        aF[i] = v;
    }
#pragma unroll
    for (int i = 0; i < BV; i++) {
        const int idx = tid + i * NT;
        const int r = idx / (TN / 4);
        const int c = (idx % (TN / 4)) * 4;
        bF[i] = *(const float4*)(B + (size_t)r * N + cb + c);
    }
#pragma unroll
    for (int i = 0; i < AV; i++) {
        const int idx = tid + i * NT;
        const int r = idx / (BK / 4);
        const int c = (idx % (BK / 4)) * 4;
        As[0][c + 0][r] = aF[i].x;
        As[0][c + 1][r] = aF[i].y;
        As[0][c + 2][r] = aF[i].z;
        As[0][c + 3][r] = aF[i].w;
    }
#pragma unroll
    for (int i = 0; i < BV; i++) {
        const int idx = tid + i * NT;
        const int r = idx / (TN / 4);
        const int c = (idx % (TN / 4)) * 4;
        *(float4*)&Bs[0][r][c] = bF[i];
    }
    __syncthreads();

    int buf = 0;
    for (int k0 = BK; k0 < K; k0 += BK) {
#pragma unroll
        for (int i = 0; i < AV; i++) {
            const int idx = tid + i * NT;
            const int r = idx / (BK / 4);
            const int c = (idx % (BK / 4)) * 4;
            float4 v = make_float4(0.f, 0.f, 0.f, 0.f);
            if (rb + r < M) v = *(const float4*)(A + (size_t)(rb + r) * K + k0 + c);
            if (bnscale) {
                float4 sc = *(const float4*)(bnscale + k0 + c);
                float4 sh = *(const float4*)(bnshift + k0 + c);
                v.x = fmaxf(fmaf(v.x, sc.x, sh.x), 0.f);
                v.y = fmaxf(fmaf(v.y, sc.y, sh.y), 0.f);
                v.z = fmaxf(fmaf(v.z, sc.z, sh.z), 0.f);
                v.w = fmaxf(fmaf(v.w, sc.w, sh.w), 0.f);
            }
            aF[i] = v;
        }
#pragma unroll
        for (int i = 0; i < BV; i++) {
            const int idx = tid + i * NT;
            const int r = idx / (TN / 4);
            const int c = (idx % (TN / 4)) * 4;
            bF[i] = *(const float4*)(B + (size_t)(k0 + r) * N + cb + c);
        }
#pragma unroll
        for (int kk = 0; kk < BK; kk++) {
            float a[8], b[8];
            *(float4*)&a[0] = *(const float4*)&As[buf][kk][ty * 4];
            *(float4*)&a[4] = *(const float4*)&As[buf][kk][TM / 2 + ty * 4];
            *(float4*)&b[0] = *(const float4*)&Bs[buf][kk][tx * 4];
            *(float4*)&b[4] = *(const float4*)&Bs[buf][kk][TN / 2 + tx * 4];
#pragma unroll
            for (int i = 0; i < 8; i++)
#pragma unroll
                for (int j = 0; j < 8; j++)
                    acc[i][j] = fmaf(a[i], b[j], acc[i][j]);
        }
#pragma unroll
        for (int i = 0; i < AV; i++) {
            const int idx = tid + i * NT;
            const int r = idx / (BK / 4);
            const int c = (idx % (BK / 4)) * 4;
            As[buf ^ 1][c + 0][r] = aF[i].x;
            As[buf ^ 1][c + 1][r] = aF[i].y;
            As[buf ^ 1][c + 2][r] = aF[i].z;
            As[buf ^ 1][c + 3][r] = aF[i].w;
        }
#pragma unroll
        for (int i = 0; i < BV; i++) {
            const int idx = tid + i * NT;
            const int r = idx / (TN / 4);
            const int c = (idx % (TN / 4)) * 4;
            *(float4*)&Bs[buf ^ 1][r][c] = bF[i];
        }
        __syncthreads();
        buf ^= 1;
    }
#pragma unroll
    for (int kk = 0; kk < BK; kk++) {
        float a[8], b[8];
        *(float4*)&a[0] = *(const float4*)&As[buf][kk][ty * 4];
        *(float4*)&a[4] = *(const float4*)&As[buf][kk][TM / 2 + ty * 4];
        *(float4*)&b[0] = *(const float4*)&Bs[buf][kk][tx * 4];
        *(float4*)&b[4] = *(const float4*)&Bs[buf][kk][TN / 2 + tx * 4];
#pragma unroll
        for (int i = 0; i < 8; i++)
#pragma unroll
            for (int j = 0; j < 8; j++)
                acc[i][j] = fmaf(a[i], b[j], acc[i][j]);
    }

#pragma unroll
    for (int i = 0; i < 8; i++) {
        int r = rb + (i < 4 ? ty * 4 + i : TM / 2 + ty * 4 + (i - 4));
        if (r < M) {
            float4 v0 = make_float4(acc[i][0], acc[i][1], acc[i][2], acc[i][3]);
            float4 v1 = make_float4(acc[i][4], acc[i][5], acc[i][6], acc[i][7]);
            *(float4*)(C + (size_t)r * N + cb + tx * 4) = v0;
            *(float4*)(C + (size_t)r * N + cb + TN / 2 + tx * 4) = v1;
        }
    }
}

// ---------------- per-(node,head) attention coefficients s,d -------------------
__global__ void k_sd(const float* __restrict__ h, const float* __restrict__ asrc,
                     const float* __restrict__ adst, int Nn, int H) {
    int w = (int)((blockIdx.x * (size_t)blockDim.x + threadIdx.x) >> 5);
    int lane = threadIdx.x & 31;
    if (w >= Nn * H) return;
    int n = w / H, hh = w - n * H;
    const float* hp = h + (size_t)n * H * 64 + hh * 64;
    float x0 = hp[lane], x1 = hp[lane + 32];
    float sv = x0 * asrc[hh * 64 + lane] + x1 * asrc[hh * 64 + lane + 32];
    float dv = x0 * adst[hh * 64 + lane] + x1 * adst[hh * 64 + lane + 32];
#pragma unroll
    for (int o = 16; o; o >>= 1) {
        sv += __shfl_xor_sync(0xffffffffu, sv, o);
        dv += __shfl_xor_sync(0xffffffffu, dv, o);
    }
    if (lane == 0) { g_s[w] = sv; g_d[w] = dv; }
}

// ---------------- online-softmax helpers ---------------------------------------
__device__ __forceinline__ void osm_upd(float& m, float& s, float e) {
    float mn = fmaxf(m, e);
    s = s * expf(m - mn) + expf(e - mn);
    m = mn;
}
__device__ __forceinline__ void osm_merge(float& m, float& s, float mo, float so) {
    float mn = fmaxf(m, mo);
    s = s * expf(m - mn) + so * expf(mo - mn);
    m = mn;
}

// ---------------- CSR softmax: warp per destination node -----------------------
__global__ void k_smax4(int Nn) {
    int w = (int)((blockIdx.x * (size_t)blockDim.x + threadIdx.x) >> 5);
    int lane = threadIdx.x & 31;
    if (w >= Nn) return;
    int rs = g_rowstart[w], re = g_rowstart[w + 1];
    float4 d4 = *(const float4*)&g_d[w * 4];
    float4 m = make_float4(-3.0e38f, -3.0e38f, -3.0e38f, -3.0e38f);
    float4 s = make_float4(0.f, 0.f, 0.f, 0.f);
    for (int p = rs + lane; p < re; p += 32) {
        int src = g_csr_src[p];
        float4 sv = *(const float4*)&g_s[src * 4];
        float4 e;
        e.x = sv.x + d4.x; e.x = e.x > 0.f ? e.x : 0.2f * e.x;
        e.y = sv.y + d4.y; e.y = e.y > 0.f ? e.y : 0.2f * e.y;
        e.z = sv.z + d4.z; e.z = e.z > 0.f ? e.z : 0.2f * e.z;
        e.w = sv.w + d4.w; e.w = e.w > 0.f ? e.w : 0.2f * e.w;
        osm_upd(m.x, s.x, e.x);
        osm_upd(m.y, s.y, e.y);
        osm_upd(m.z, s.z, e.z);
        osm_upd(m.w, s.w, e.w);
    }
#pragma unroll
    for (int o = 16; o; o >>= 1) {
        float mo, so;
        mo = __shfl_xor_sync(0xffffffffu, m.x, o); so = __shfl_xor_sync(0xffffffffu, s.x, o);
        osm_merge(m.x, s.x, mo, so);
        mo = __shfl_xor_sync(0xffffffffu, m.y, o); so = __shfl_xor_sync(0xffffffffu, s.y, o);
        osm_merge(m.y, s.y, mo, so);
        mo = __shfl_xor_sync(0xffffffffu, m.z, o); so = __shfl_xor_sync(0xffffffffu, s.z, o);
        osm_merge(m.z, s.z, mo, so);
        mo = __shfl_xor_sync(0xffffffffu, m.w, o); so = __shfl_xor_sync(0xffffffffu, s.w, o);
        osm_merge(m.w, s.w, mo, so);
    }
    if (lane == 0) {
        *(float4*)&g_m[w * 4] = m;
        *(float4*)&g_den[w * 4] = s;
    }
}

__global__ void k_smax1(int Nn) {
    int w = (int)((blockIdx.x * (size_t)blockDim.x + threadIdx.x) >> 5);
    int lane = threadIdx.x & 31;
    if (w >= Nn) return;
    int rs = g_rowstart[w], re = g_rowstart[w + 1];
    float dv = g_d[w];
    float m = -3.0e38f, s = 0.f;
    for (int p = rs + lane; p < re; p += 32) {
        int src = g_csr_src[p];
        float e = g_s[src] + dv;
        e = e > 0.f ? e : 0.2f * e;
        osm_upd(m, s, e);
    }
#pragma unroll
    for (int o = 16; o; o >>= 1) {
        float mo = __shfl_xor_sync(0xffffffffu, m, o);
        float so = __shfl_xor_sync(0xffffffffu, s, o);
        osm_merge(m, s, mo, so);
    }
    if (lane == 0) { g_m[w] = m; g_den[w] = s; }
}

// ---------------- CSR aggregation: warp per destination, no atomics ------------
__global__ void k_aggr_csr256(int Nn) {
    int w = (int)((blockIdx.x * (size_t)blockDim.x + threadIdx.x) >> 5);
    int lane = threadIdx.x & 31;
    if (w >= Nn) return;
    int rs = g_rowstart[w], re = g_rowstart[w + 1];
    float4 d4 = *(const float4*)&g_d[w * 4];
    float4 m4 = *(const float4*)&g_m[w * 4];
    float4 den = *(const float4*)&g_den[w * 4];
    float4 ri;
    ri.x = 1.f / (den.x + 1e-16f);
    ri.y = 1.f / (den.y + 1e-16f);
    ri.z = 1.f / (den.z + 1e-16f);
    ri.w = 1.f / (den.w + 1e-16f);
    float4 acc0 = make_float4(0.f, 0.f, 0.f, 0.f);
    float4 acc1 = make_float4(0.f, 0.f, 0.f, 0.f);
    bool hi = (lane >= 16);
    for (int p = rs; p < re; p++) {
        int src = g_csr_src[p];                     // uniform across warp
        float4 sv = *(const float4*)&g_s[src * 4];  // broadcast load
        float4 e;
        e.x = sv.x + d4.x; e.x = e.x > 0.f ? e.x : 0.2f * e.x;
        e.y = sv.y + d4.y; e.y = e.y > 0.f ? e.y : 0.2f * e.y;
        e.z = sv.z + d4.z; e.z = e.z > 0.f ? e.z : 0.2f * e.z;
        e.w = sv.w + d4.w; e.w = e.w > 0.f ? e.w : 0.2f * e.w;
        float4 a;
        a.x = expf(e.x - m4.x) * ri.x;
        a.y = expf(e.y - m4.y) * ri.y;
        a.z = expf(e.z - m4.z) * ri.z;
        a.w = expf(e.w - m4.w) * ri.w;
        float a0 = hi ? a.y : a.x;   // head of channels [4*lane ..]
        float a1 = hi ? a.w : a.z;   // head of channels [128+4*lane ..]
        const float4* hp = (const float4*)(g_bufA + (size_t)src * 256);
        float4 v0 = hp[lane], v1 = hp[lane + 32];
        acc0.x = fmaf(a0, v0.x, acc0.x); acc0.y = fmaf(a0, v0.y, acc0.y);
        acc0.z = fmaf(a0, v0.z, acc0.z); acc0.w = fmaf(a0, v0.w, acc0.w);
        acc1.x = fmaf(a1, v1.x, acc1.x); acc1.y = fmaf(a1, v1.y, acc1.y);
        acc1.z = fmaf(a1, v1.z, acc1.z); acc1.w = fmaf(a1, v1.w, acc1.w);
    }
    float4* op = (float4*)(g_bufB + (size_t)w * 256);
    op[lane] = acc0;
    op[lane + 32] = acc1;
}

__global__ void k_aggr_csr64(int Nn) {
    int w = (int)((blockIdx.x * (size_t)blockDim.x + threadIdx.x) >> 5);
    int lane = threadIdx.x & 31;
    if (w >= Nn) return;
    int rs = g_rowstart[w], re = g_rowstart[w + 1];
    float dv = g_d[w];
    float m = g_m[w];
    float ri = 1.f / (g_den[w] + 1e-16f);
    float2 acc = make_float2(0.f, 0.f);
    for (int p = rs; p < re; p++) {
        int src = g_csr_src[p];
        float e = g_s[src] + dv;
        e = e > 0.f ? e : 0.2f * e;
        float a = expf(e - m) * ri;
        float2 v = ((const float2*)(g_bufA + (size_t)src * 64))[lane];
        acc.x = fmaf(a, v.x, acc.x);
        acc.y = fmaf(a, v.y, acc.y);
    }
    ((float2*)(g_bufB + (size_t)w * 64))[lane] = acc;
}

// ---------------- batchnorm stats (on x + bias) --------------------------------
__global__ void k_bnstats(const float* __restrict__ X, const float* __restrict__ bias,
                          int Nn, int HC) {
    int tid = threadIdx.x;
    int ch = tid & (HC - 1);
    int rpb = blockDim.x / HC;
    int r = blockIdx.x * rpb + tid / HC;
    int stride = gridDim.x * rpb;
    float b = bias[ch];
    float s = 0.f, q = 0.f;
    for (; r < Nn; r += stride) {
        float x = X[(size_t)r * HC + ch] + b;
        s += x; q += x * x;
    }
    atomicAdd(&g_sum[ch], (double)s);
    atomicAdd(&g_sq[ch], (double)q);
}

__global__ void k_bnfin(const float* __restrict__ gamma, const float* __restrict__ beta,
                        const float* __restrict__ bias, int Nn, int HC) {
    int ch = threadIdx.x;
    if (ch >= HC) return;
    double mu = g_sum[ch] / Nn;
    double var = g_sq[ch] / Nn - mu * mu;
    float sc = (float)((double)gamma[ch] / sqrt(var + 1e-5));
    g_scale[ch] = sc;
    g_shift[ch] = beta[ch] + sc * (bias[ch] - (float)mu);
}

// ---------------- pooling (applies layer-2 BN + ReLU inline) -------------------
__global__ void k_initpool() {
    int i = threadIdx.x;
    if (i < 64) { g_pmax[i] = -INFINITY; g_psum[i] = 0.0; }
}

__global__ void k_pool(const float* __restrict__ X, int Nn) {
    int tid = threadIdx.x;
    int ch = tid & 63;
    int rpb = blockDim.x >> 6;
    int r = blockIdx.x * rpb + (tid >> 6);
    int stride = gridDim.x * rpb;
    float sc = g_scale[ch], sh = g_shift[ch];
    float s = 0.f, mx = -INFINITY;
    for (; r < Nn; r += stride) {
        float x = fmaxf(fmaf(X[(size_t)r * 64 + ch], sc, sh), 0.f);
        s += x; mx = fmaxf(mx, x);
    }
    atomicAdd(&g_psum[ch], (double)s);
    atomicMaxF(&g_pmax[ch], mx);
}

// ---------------- classifier (single block) ------------------------------------
__global__ void k_cls(const float* __restrict__ Wc1, const float* __restrict__ bc1,
                      const float* __restrict__ Wc2, const float* __restrict__ bc2,
                      int Nn, float* __restrict__ out) {
    __shared__ float pooled[128];
    __shared__ float z[64];
    int t = threadIdx.x;
    if (t < 64) pooled[t] = (float)(g_psum[t] / Nn);
    else        pooled[t] = g_pmax[t - 64];
    __syncthreads();
    if (t < 64) {
        float acc = bc1[t];
        for (int k = 0; k < 128; k++) acc += pooled[k] * Wc1[k * 64 + t];
        z[t] = fmaxf(acc, 0.f);
    }
    __syncthreads();
    if (t < 2) {
        float acc = bc2[t];
        for (int j = 0; j < 64; j++) acc += z[j] * Wc2[j * 2 + t];
        out[t] = acc;
    }
}

// ---------------- driver -------------------------------------------------------
extern "C" void kernel_launch(void* const* d_in, const int* in_sizes, int n_in,
                              void* d_out, int out_size) {
    const float* x   = (const float*)d_in[0];
    const int*   ei  = (const int*)d_in[1];   // int32 OR little-endian int64; detected on device
    const float* W0  = (const float*)d_in[2];  const float* b0  = (const float*)d_in[3];
    const float* as0 = (const float*)d_in[4];  const float* ad0 = (const float*)d_in[5];
    const float* gm0 = (const float*)d_in[6];  const float* bt0 = (const float*)d_in[7];
    const float* W1  = (const float*)d_in[8];  const float* b1  = (const float*)d_in[9];
    const float* as1 = (const float*)d_in[10]; const float* ad1 = (const float*)d_in[11];
    const float* gm1 = (const float*)d_in[12]; const float* bt1 = (const float*)d_in[13];
    const float* W2  = (const float*)d_in[14]; const float* b2  = (const float*)d_in[15];
    const float* as2 = (const float*)d_in[16]; const float* ad2 = (const float*)d_in[17];
    const float* gm2 = (const float*)d_in[18]; const float* bt2 = (const float*)d_in[19];
    const float* Wc1 = (const float*)d_in[20]; const float* bc1 = (const float*)d_in[21];
    const float* Wc2 = (const float*)d_in[22]; const float* bc2 = (const float*)d_in[23];

    const int Nn = in_sizes[0] / 128;
    const int E  = in_sizes[1] / 2;
    const int ET = E + Nn;

    float* bufA; float* bufB; float* scaleP; float* shiftP;
    void *sumP, *sqP, *psumP, *degP;
    cudaGetSymbolAddress((void**)&bufA, g_bufA);
    cudaGetSymbolAddress((void**)&bufB, g_bufB);
    cudaGetSymbolAddress((void**)&scaleP, g_scale);
    cudaGetSymbolAddress((void**)&shiftP, g_shift);
    cudaGetSymbolAddress(&sumP, g_sum);
    cudaGetSymbolAddress(&sqP, g_sq);
    cudaGetSymbolAddress(&psumP, g_psum);
    cudaGetSymbolAddress(&degP, g_deg);

    // Resolve edge_index dtype, materialize src/dst (+self-loops), build CSR by dst
    k_detect<<<1, 32>>>(ei);
    k_cvt<<<(ET + 255) / 256, 256>>>(ei, E, ET);
    cudaMemsetAsync(degP, 0, Nn * sizeof(int), 0);
    k_hist<<<(ET + 255) / 256, 256>>>(ET);
    k_scan<<<1, 1024>>>(Nn);
    k_scatter<<<(ET + 255) / 256, 256>>>(ET);

    const unsigned nwb = (unsigned)(((long long)Nn * 32 + 255) / 256);  // warp-per-node grids

    auto run_layer = [&](const float* in, int K, const float* W, const float* bias,
                         const float* asrc, const float* adst,
                         const float* gamma, const float* beta, int H, bool bnA) {
        const int HC = H * 64;
        const float* sc = bnA ? scaleP : nullptr;
        const float* sh = bnA ? shiftP : nullptr;
        if (HC == 256)
            k_sgemm_opt<128, 128><<<dim3(2, (Nn + 127) / 128), 256>>>(in, W, bufA, Nn, 256, K, sc, sh);
        else
            k_sgemm_opt<128, 64><<<dim3(1, (Nn + 127) / 128), 128>>>(in, W, bufA, Nn, 64, K, sc, sh);
        {
            long long th = (long long)Nn * H * 32;
            k_sd<<<(unsigned)((th + 255) / 256), 256>>>(bufA, asrc, adst, Nn, H);
        }
        if (H == 4) {
            k_smax4<<<nwb, 256>>>(Nn);
            k_aggr_csr256<<<nwb, 256>>>(Nn);
        } else {
            k_smax1<<<nwb, 256>>>(Nn);
            k_aggr_csr64<<<nwb, 256>>>(Nn);
        }
        cudaMemsetAsync(sumP, 0, HC * sizeof(double), 0);
        cudaMemsetAsync(sqP, 0, HC * sizeof(double), 0);
        k_bnstats<<<512, 256>>>(bufB, bias, Nn, HC);
        k_bnfin<<<1, 256>>>(gamma, beta, bias, Nn, HC);
        // No normalize pass — BN+ReLU is consumed by the next GEMM / k_pool.
    };

    run_layer(x,    128, W0, b0, as0, ad0, gm0, bt0, 4, false);
    run_layer(bufB, 256, W1, b1, as1, ad1, gm1, bt1, 4, true);
    run_layer(bufB, 256, W2, b2, as2, ad2, gm2, bt2, 1, true);

    cudaMemsetAsync(psumP, 0, 64 * sizeof(double), 0);
    k_initpool<<<1, 64>>>();
    k_pool<<<256, 256>>>(bufB, Nn);   // applies layer-2 BN+ReLU inline
    k_cls<<<1, 128>>>(Wc1, bc1, Wc2, bc2, Nn, (float*)d_out);
}